// round 8
// baseline (speedup 1.0000x reference)
#include <cuda_runtime.h>
#include <cstdint>

#define NPTS 8192
#define DIM  512
#define MARGINF 0.3f

#define BM 128
#define BN 128
#define BKB 128                  // int8 elems (=bytes) per K chunk
#define NCHUNK (DIM/BKB)         // 4
#define GB (NPTS/BM)             // 64
#define NPART (GB*(GB+1)/2)      // 2080 upper-triangular tiles

#define STAGES 3
#define STAGE_BYTES 32768        // 16KB A + 16KB B
#define SMEM_BYTES (1024 + STAGES*STAGE_BYTES)

#define QSCALE   (5.5f/127.0f)           // int8 step
#define QINV     (127.0f/5.5f)
#define QS2      (QSCALE*QSCALE)         // sim = QS2 * s32dot

// ---------------- device scratch (no allocations allowed) ----------------
__device__ uint8_t g_X[NPTS*DIM];   // 4 MB int8 copy of inputs
__device__ int   g_lab[NPTS];
__device__ float g_part[NPART];

// ---------------- helpers ----------------
__device__ __forceinline__ uint32_t smem_u32(const void* p){
    uint32_t a;
    asm("{ .reg .u64 t; cvta.to.shared.u64 t, %1; cvt.u32.u64 %0, t; }"
        : "=r"(a) : "l"(p));
    return a;
}
#define SW128(o) ((o) ^ (((o) >> 3) & 0x70))

__device__ __forceinline__ void cp16(uint32_t s, const void* g){
    asm volatile("cp.async.cg.shared.global [%0], [%1], 16;" :: "r"(s), "l"(g));
}
#define CP_COMMIT() asm volatile("cp.async.commit_group;" ::: "memory")
#define CP_WAIT(n)  asm volatile("cp.async.wait_group %0;" :: "n"(n) : "memory")

__device__ __forceinline__ void ldm_x4(uint32_t* r, uint32_t addr){
    asm volatile("ldmatrix.sync.aligned.m8n8.x4.shared.b16 {%0,%1,%2,%3}, [%4];"
                 : "=r"(r[0]), "=r"(r[1]), "=r"(r[2]), "=r"(r[3]) : "r"(addr));
}
// m16n8k32 s8 IMMA, exact s32 accumulate
__device__ __forceinline__ void mma_s8(int* d, const uint32_t* a,
                                       uint32_t b0, uint32_t b1){
    asm volatile(
        "mma.sync.aligned.m16n8k32.row.col.s32.s8.s8.s32 "
        "{%0,%1,%2,%3}, {%4,%5,%6,%7}, {%8,%9}, {%0,%1,%2,%3};"
        : "+r"(d[0]), "+r"(d[1]), "+r"(d[2]), "+r"(d[3])
        : "r"(a[0]), "r"(a[1]), "r"(a[2]), "r"(a[3]), "r"(b0), "r"(b1));
}
__device__ __forceinline__ int q8(float x){
    const float s = fminf(fmaxf(x * QINV, -127.f), 127.f);
    return __float2int_rn(s);
}

// ---------------- kernel 1: quantize inputs to int8 + normalize labels ----------------
__global__ void prep_kernel(const float* __restrict__ x, const void* __restrict__ tgt){
    const int idx = blockIdx.x * blockDim.x + threadIdx.x;   // NPTS*DIM/4 threads
    const float4 v = ((const float4*)x)[idx];
    const int i0 = q8(v.x), i1 = q8(v.y), i2 = q8(v.z), i3 = q8(v.w);
    ((uint32_t*)g_X)[idx] = (uint32_t)(i0 & 255) | ((uint32_t)(i1 & 255) << 8)
                          | ((uint32_t)(i2 & 255) << 16) | ((uint32_t)i3 << 24);

    if (blockIdx.x == 0){
        // detect int64 vs int32 labels: values in [0,128); if int64, all odd words are 0
        const int* w = (const int*)tgt;
        bool is64 = true;
        #pragma unroll 1
        for (int k = 0; k < 64; k++)
            if (w[2*k + 1] != 0) { is64 = false; break; }
        if (is64){
            const long long* t64 = (const long long*)tgt;
            for (int i = threadIdx.x; i < NPTS; i += blockDim.x)
                g_lab[i] = (int)t64[i];
        } else {
            for (int i = threadIdx.x; i < NPTS; i += blockDim.x)
                g_lab[i] = w[i];
        }
    }
}

// ---------------- kernel 2: int8 IMMA GEMM (upper-tri tiles) + fused masked loss ----------------
__global__ void __launch_bounds__(256, 2) contrastive_gemm(){
    extern __shared__ char smem[];
    const uint32_t sb = smem_u32(smem);
    const int tid = threadIdx.x;
    const int wid = tid >> 5, lane = tid & 31;

    // map blockIdx.x -> upper-triangular (bi, bj), bi <= bj
    int bi = 0, rem = blockIdx.x;
    while (rem >= GB - bi){ rem -= GB - bi; bi++; }
    const int bj = bi + rem;
    const int i0 = bi * BM, j0 = bj * BN;
    const bool diag = (bi == bj);

    // labels into smem: ilab[128] @0, jlab[128] @512
    int* ilab = (int*)smem;
    int* jlab = (int*)(smem + 512);
    if (tid < 128) ilab[tid] = g_lab[i0 + tid];
    else           jlab[tid - 128] = g_lab[j0 + (tid - 128)];

    // cp.async loader: 256 threads, 8 threads x 16B per 128B row, 32 rows/pass
    const int rr = tid >> 3, vv = tid & 7;
    auto load_stage = [&](int c){
        const uint32_t sA = sb + 1024 + (c % STAGES) * STAGE_BYTES;
        const uint32_t sB = sA + 16384;
        const int kc = c * BKB;
        #pragma unroll
        for (int p = 0; p < 4; p++){
            const int r = rr + p * 32;
            cp16(sA + SW128(r * 128 + vv * 16),
                 g_X + (size_t)(i0 + r) * DIM + kc + vv * 16);
            cp16(sB + SW128(r * 128 + vv * 16),
                 g_X + (size_t)(j0 + r) * DIM + kc + vv * 16);
        }
    };

    load_stage(0); CP_COMMIT();
    load_stage(1); CP_COMMIT();

    const int wm0 = (wid & 3) * 32;     // 4 warps in M
    const int wn0 = (wid >> 2) * 64;    // 2 warps in N

    int acc[2][8][4];                   // exact s32 accumulators (warp tile 32x64)
    #pragma unroll
    for (int tm = 0; tm < 2; tm++)
        #pragma unroll
        for (int tn = 0; tn < 8; tn++)
            #pragma unroll
            for (int e = 0; e < 4; e++) acc[tm][tn][e] = 0;

    const int lrow = lane & 15, lhi = lane >> 4;

    for (int c = 0; c < NCHUNK; c++){
        CP_WAIT(1);
        __syncthreads();                 // single barrier per chunk (3-stage proof)
        if (c + 2 < NCHUNK) load_stage(c + 2);
        CP_COMMIT();                     // empty commits keep group count aligned

        const uint32_t sA = sb + 1024 + (c % STAGES) * STAGE_BYTES;
        const uint32_t sB = sA + 16384;
        #pragma unroll
        for (int ks = 0; ks < 4; ks++){
            const int cb = ks * 32 + lhi * 16;     // 32 B = k32 int8 per mma
            uint32_t a[2][4];
            #pragma unroll
            for (int tm = 0; tm < 2; tm++)
                ldm_x4(a[tm], sA + SW128((wm0 + tm * 16 + lrow) * 128 + cb));
            uint32_t b[4][4];
            #pragma unroll
            for (int tp = 0; tp < 4; tp++)
                ldm_x4(b[tp], sB + SW128((wn0 + tp * 16 + lrow) * 128 + cb));
            #pragma unroll
            for (int tm = 0; tm < 2; tm++)
                #pragma unroll
                for (int tp = 0; tp < 4; tp++){
                    mma_s8(acc[tm][2*tp],     a[tm], b[tp][0], b[tp][2]);
                    mma_s8(acc[tm][2*tp + 1], a[tm], b[tp][1], b[tp][3]);
                }
        }
    }

    // ---------------- fused masked loss on register accumulators ----------------
    const int r0 = lane >> 2, c0 = (lane & 3) * 2;
    float loss = 0.f;
    #pragma unroll
    for (int tm = 0; tm < 2; tm++){
        const int rowA = wm0 + tm * 16 + r0;
        const int liA  = ilab[rowA];
        const int liB  = ilab[rowA + 8];
        #pragma unroll
        for (int tn = 0; tn < 8; tn++){
            const int colb = wn0 + tn * 8 + c0;
            const int lj0 = jlab[colb], lj1 = jlab[colb + 1];
            #pragma unroll
            for (int e = 0; e < 4; e++){
                const float v = (float)acc[tm][tn][e] * QS2;
                const int row = (e >> 1) ? rowA + 8 : rowA;
                const int li  = (e >> 1) ? liB : liA;
                const int lj  = (e & 1) ? lj1 : lj0;
                float w = 2.f;
                if (diag){
                    const int gi = row, gj = colb + (e & 1);
                    w = (gi < gj) ? 2.f : ((gi == gj) ? 1.f : 0.f);
                }
                float l;
                if (li == lj) l = (v < 1.f) ? (1.f - v) : 0.f;
                else          l = (v > MARGINF) ? v : 0.f;
                loss += w * l;
            }
        }
    }

    // block reduction -> per-tile partial
    #pragma unroll
    for (int o = 16; o; o >>= 1) loss += __shfl_xor_sync(0xffffffffu, loss, o);
    float* wsum = (float*)(smem + 768);
    if (lane == 0) wsum[wid] = loss;
    __syncthreads();
    if (tid == 0){
        float s = 0.f;
        #pragma unroll
        for (int w = 0; w < 8; w++) s += wsum[w];
        g_part[blockIdx.x] = s;
    }
}

// ---------------- kernel 3: deterministic final reduction ----------------
__global__ void reduce_kernel(float* __restrict__ out){
    __shared__ float sm[512];
    const int t = threadIdx.x;
    float v = 0.f;
    for (int i = t; i < NPART; i += 512) v += g_part[i];
    sm[t] = v;
    __syncthreads();
    for (int s = 256; s > 0; s >>= 1){
        if (t < s) sm[t] += sm[t + s];
        __syncthreads();
    }
    if (t == 0) out[0] = sm[0] / (float)NPTS;
}

// ---------------- launch ----------------
extern "C" void kernel_launch(void* const* d_in, const int* in_sizes, int n_in,
                              void* d_out, int out_size){
    const float* x   = (const float*)d_in[0];
    const void*  tgt = d_in[1];
    float* out = (float*)d_out;

    cudaFuncSetAttribute(contrastive_gemm,
                         cudaFuncAttributeMaxDynamicSharedMemorySize, SMEM_BYTES);

    prep_kernel<<<NPTS*DIM/1024, 256>>>(x, tgt);
    contrastive_gemm<<<NPART, 256, SMEM_BYTES>>>();
    reduce_kernel<<<1, 512>>>(out);
}

// round 9
// speedup vs baseline: 1.8686x; 1.8686x over previous
#include <cuda_runtime.h>
#include <cuda_bf16.h>
#include <cstdint>

#define NPTS 8192
#define DIM  512
#define MARGINF 0.3f

#define BM 128
#define BN 128
#define BK 64                    // bf16 elems per K chunk (128 B per row)
#define NCHUNK (DIM/BK)          // 8
#define GB (NPTS/BM)             // 64
#define NPART (GB*(GB+1)/2)      // 2080 upper-triangular tiles

#define STAGES 3
#define STAGE_BYTES 32768        // 16KB A + 16KB B
#define SMEM_BYTES (1024 + STAGES*STAGE_BYTES)

// ---------------- device scratch (no allocations allowed) ----------------
__device__ __nv_bfloat16 g_X[NPTS*DIM];   // 8 MB bf16 copy of inputs
__device__ int   g_lab[NPTS];
__device__ float g_part[NPART];
__device__ int   g_cnt = 0;               // CTA-done counter (reset after use)

// ---------------- helpers ----------------
__device__ __forceinline__ uint32_t smem_u32(const void* p){
    uint32_t a;
    asm("{ .reg .u64 t; cvta.to.shared.u64 t, %1; cvt.u32.u64 %0, t; }"
        : "=r"(a) : "l"(p));
    return a;
}
#define SW128(o) ((o) ^ (((o) >> 3) & 0x70))

__device__ __forceinline__ void cp16(uint32_t s, const void* g){
    asm volatile("cp.async.cg.shared.global [%0], [%1], 16;" :: "r"(s), "l"(g));
}
#define CP_COMMIT() asm volatile("cp.async.commit_group;" ::: "memory")
#define CP_WAIT(n)  asm volatile("cp.async.wait_group %0;" :: "n"(n) : "memory")

__device__ __forceinline__ void ldm_x4(uint32_t* r, uint32_t addr){
    asm volatile("ldmatrix.sync.aligned.m8n8.x4.shared.b16 {%0,%1,%2,%3}, [%4];"
                 : "=r"(r[0]), "=r"(r[1]), "=r"(r[2]), "=r"(r[3]) : "r"(addr));
}
__device__ __forceinline__ void mma16816(float* d, const uint32_t* a,
                                         uint32_t b0, uint32_t b1){
    asm volatile(
        "mma.sync.aligned.m16n8k16.row.col.f32.bf16.bf16.f32 "
        "{%0,%1,%2,%3}, {%4,%5,%6,%7}, {%8,%9}, {%0,%1,%2,%3};"
        : "+f"(d[0]), "+f"(d[1]), "+f"(d[2]), "+f"(d[3])
        : "r"(a[0]), "r"(a[1]), "r"(a[2]), "r"(a[3]), "r"(b0), "r"(b1));
}

// ---------------- kernel 1: convert inputs to bf16 + normalize labels ----------------
// 2048 blocks x 256 threads; each thread: 2 float4 loads -> 1 uint4 (16B) store
__global__ void prep_kernel(const float* __restrict__ x, const void* __restrict__ tgt){
    const int idx = blockIdx.x * blockDim.x + threadIdx.x;   // NPTS*DIM/8 threads
    const float4 v0 = ((const float4*)x)[2*idx];
    const float4 v1 = ((const float4*)x)[2*idx + 1];
    __nv_bfloat162 p0 = __float22bfloat162_rn(make_float2(v0.x, v0.y));
    __nv_bfloat162 p1 = __float22bfloat162_rn(make_float2(v0.z, v0.w));
    __nv_bfloat162 p2 = __float22bfloat162_rn(make_float2(v1.x, v1.y));
    __nv_bfloat162 p3 = __float22bfloat162_rn(make_float2(v1.z, v1.w));
    uint4 st;
    st.x = *(uint32_t*)&p0;
    st.y = *(uint32_t*)&p1;
    st.z = *(uint32_t*)&p2;
    st.w = *(uint32_t*)&p3;
    ((uint4*)g_X)[idx] = st;

    if (blockIdx.x == 0){
        // detect int64 vs int32 labels: values in [0,128); if int64, all odd words are 0
        const int* w = (const int*)tgt;
        bool is64 = true;
        #pragma unroll 1
        for (int k = 0; k < 64; k++)
            if (w[2*k + 1] != 0) { is64 = false; break; }
        if (is64){
            const long long* t64 = (const long long*)tgt;
            for (int i = threadIdx.x; i < NPTS; i += blockDim.x)
                g_lab[i] = (int)t64[i];
        } else {
            for (int i = threadIdx.x; i < NPTS; i += blockDim.x)
                g_lab[i] = w[i];
        }
    }
}

// ---------------- kernel 2: bf16 HMMA GEMM + fused loss + last-CTA reduction ----------------
__global__ void __launch_bounds__(256, 2) contrastive_gemm(float* __restrict__ out){
    extern __shared__ char smem[];
    const uint32_t sb = smem_u32(smem);
    const int tid = threadIdx.x;
    const int wid = tid >> 5, lane = tid & 31;

    // map blockIdx.x -> upper-triangular (bi, bj), bi <= bj
    int bi = 0, rem = blockIdx.x;
    while (rem >= GB - bi){ rem -= GB - bi; bi++; }
    const int bj = bi + rem;
    const int i0 = bi * BM, j0 = bj * BN;
    const bool diag = (bi == bj);

    // labels into smem: ilab[128] @0, jlab[128] @512
    int* ilab = (int*)smem;
    int* jlab = (int*)(smem + 512);
    if (tid < 128) ilab[tid] = g_lab[i0 + tid];
    else           jlab[tid - 128] = g_lab[j0 + (tid - 128)];

    // cp.async loader: 256 threads, 8 threads x 16B per 128B row, 32 rows/pass
    const int rr = tid >> 3, vv = tid & 7;
    auto load_stage = [&](int c){
        const uint32_t sA = sb + 1024 + (c % STAGES) * STAGE_BYTES;
        const uint32_t sB = sA + 16384;
        const int kc = c * BK;
        #pragma unroll
        for (int p = 0; p < 4; p++){
            const int r = rr + p * 32;
            cp16(sA + SW128(r * 128 + vv * 16),
                 g_X + (size_t)(i0 + r) * DIM + kc + vv * 8);
            cp16(sB + SW128(r * 128 + vv * 16),
                 g_X + (size_t)(j0 + r) * DIM + kc + vv * 8);
        }
    };

    load_stage(0); CP_COMMIT();
    load_stage(1); CP_COMMIT();

    const int wm0 = (wid & 3) * 32;     // 4 warps in M
    const int wn0 = (wid >> 2) * 64;    // 2 warps in N

    float acc[2][8][4];                 // warp tile 32x64
    #pragma unroll
    for (int tm = 0; tm < 2; tm++)
        #pragma unroll
        for (int tn = 0; tn < 8; tn++)
            #pragma unroll
            for (int e = 0; e < 4; e++) acc[tm][tn][e] = 0.f;

    const int lrow = lane & 15, lhi = lane >> 4;

    for (int c = 0; c < NCHUNK; c++){
        CP_WAIT(1);
        __syncthreads();                 // single barrier per chunk (3-stage proof)
        if (c + 2 < NCHUNK) load_stage(c + 2);
        CP_COMMIT();                     // empty commits keep group count aligned

        const uint32_t sA = sb + 1024 + (c % STAGES) * STAGE_BYTES;
        const uint32_t sB = sA + 16384;
        #pragma unroll
        for (int ks = 0; ks < 4; ks++){
            const int cb = ks * 32 + lhi * 16;
            uint32_t a[2][4];
            #pragma unroll
            for (int tm = 0; tm < 2; tm++)
                ldm_x4(a[tm], sA + SW128((wm0 + tm * 16 + lrow) * 128 + cb));
            uint32_t b[4][4];
            #pragma unroll
            for (int tp = 0; tp < 4; tp++)
                ldm_x4(b[tp], sB + SW128((wn0 + tp * 16 + lrow) * 128 + cb));
            #pragma unroll
            for (int tm = 0; tm < 2; tm++)
                #pragma unroll
                for (int tp = 0; tp < 4; tp++){
                    mma16816(acc[tm][2*tp],     a[tm], b[tp][0], b[tp][2]);
                    mma16816(acc[tm][2*tp + 1], a[tm], b[tp][1], b[tp][3]);
                }
        }
    }

    // ---------------- fused masked loss on register accumulators ----------------
    const int r0 = lane >> 2, c0 = (lane & 3) * 2;
    float loss = 0.f;
    #pragma unroll
    for (int tm = 0; tm < 2; tm++){
        const int rowA = wm0 + tm * 16 + r0;
        const int liA  = ilab[rowA];
        const int liB  = ilab[rowA + 8];
        #pragma unroll
        for (int tn = 0; tn < 8; tn++){
            const int colb = wn0 + tn * 8 + c0;
            const int lj0 = jlab[colb], lj1 = jlab[colb + 1];
            #pragma unroll
            for (int e = 0; e < 4; e++){
                const float v = acc[tm][tn][e];
                const int row = (e >> 1) ? rowA + 8 : rowA;
                const int li  = (e >> 1) ? liB : liA;
                const int lj  = (e & 1) ? lj1 : lj0;
                float w = 2.f;
                if (diag){
                    const int gi = row, gj = colb + (e & 1);
                    w = (gi < gj) ? 2.f : ((gi == gj) ? 1.f : 0.f);
                }
                float l;
                if (li == lj) l = (v < 1.f) ? (1.f - v) : 0.f;
                else          l = (v > MARGINF) ? v : 0.f;
                loss += w * l;
            }
        }
    }

    // block reduction -> per-tile partial
    #pragma unroll
    for (int o = 16; o; o >>= 1) loss += __shfl_xor_sync(0xffffffffu, loss, o);
    float* wsum = (float*)(smem + 768);
    if (lane == 0) wsum[wid] = loss;
    __syncthreads();
    if (tid == 0){
        float s = 0.f;
        #pragma unroll
        for (int w = 0; w < 8; w++) s += wsum[w];
        g_part[blockIdx.x] = s;
    }

    // ---------------- last-CTA-done deterministic final reduction ----------------
    __shared__ int s_last;
    __threadfence();                     // publish g_part before counting
    if (tid == 0){
        const int done = atomicAdd(&g_cnt, 1);
        s_last = (done == NPART - 1);
    }
    __syncthreads();
    if (s_last){
        float v = 0.f;
        for (int i = tid; i < NPART; i += 256) v += *((volatile float*)&g_part[i]);
        #pragma unroll
        for (int o = 16; o; o >>= 1) v += __shfl_xor_sync(0xffffffffu, v, o);
        if (lane == 0) wsum[wid] = v;
        __syncthreads();
        if (tid == 0){
            float s = 0.f;
            #pragma unroll
            for (int w = 0; w < 8; w++) s += wsum[w];
            out[0] = s / (float)NPTS;
            g_cnt = 0;                   // reset for next graph replay
        }
    }
}

// ---------------- launch ----------------
extern "C" void kernel_launch(void* const* d_in, const int* in_sizes, int n_in,
                              void* d_out, int out_size){
    const float* x   = (const float*)d_in[0];
    const void*  tgt = d_in[1];
    float* out = (float*)d_out;

    cudaFuncSetAttribute(contrastive_gemm,
                         cudaFuncAttributeMaxDynamicSharedMemorySize, SMEM_BYTES);

    prep_kernel<<<NPTS*DIM/2048, 256>>>(x, tgt);
    contrastive_gemm<<<NPART, 256, SMEM_BYTES>>>(out);
}

// round 10
// speedup vs baseline: 2.2561x; 1.2073x over previous
#include <cuda_runtime.h>
#include <cuda_bf16.h>
#include <cstdint>

#define NPTS 8192
#define DIM  512
#define MARGINF 0.3f

#define BM 128
#define BN 128
#define BK 64                    // bf16 elems per K chunk (128 B per row)
#define NCHUNK (DIM/BK)          // 8
#define GB (NPTS/BM)             // 64
#define NPART (GB*(GB+1)/2)      // 2080 upper-triangular tiles

#define STAGES 3
#define STAGE_BYTES 32768        // 16KB A + 16KB B
#define SMEM_BYTES (1024 + STAGES*STAGE_BYTES)

// ---------------- device scratch (no allocations allowed) ----------------
__device__ __nv_bfloat16 g_X[NPTS*DIM];   // 8 MB bf16 copy of inputs
__device__ int   g_lab[NPTS];
__device__ float g_part[NPART];

// ---------------- helpers ----------------
__device__ __forceinline__ uint32_t smem_u32(const void* p){
    uint32_t a;
    asm("{ .reg .u64 t; cvta.to.shared.u64 t, %1; cvt.u32.u64 %0, t; }"
        : "=r"(a) : "l"(p));
    return a;
}
#define SW128(o) ((o) ^ (((o) >> 3) & 0x70))

__device__ __forceinline__ void cp16(uint32_t s, const void* g){
    asm volatile("cp.async.cg.shared.global [%0], [%1], 16;" :: "r"(s), "l"(g));
}
#define CP_COMMIT() asm volatile("cp.async.commit_group;" ::: "memory")
#define CP_WAIT(n)  asm volatile("cp.async.wait_group %0;" :: "n"(n) : "memory")

__device__ __forceinline__ void ldm_x4(uint32_t* r, uint32_t addr){
    asm volatile("ldmatrix.sync.aligned.m8n8.x4.shared.b16 {%0,%1,%2,%3}, [%4];"
                 : "=r"(r[0]), "=r"(r[1]), "=r"(r[2]), "=r"(r[3]) : "r"(addr));
}
__device__ __forceinline__ void mma16816(float* d, const uint32_t* a,
                                         uint32_t b0, uint32_t b1){
    asm volatile(
        "mma.sync.aligned.m16n8k16.row.col.f32.bf16.bf16.f32 "
        "{%0,%1,%2,%3}, {%4,%5,%6,%7}, {%8,%9}, {%0,%1,%2,%3};"
        : "+f"(d[0]), "+f"(d[1]), "+f"(d[2]), "+f"(d[3])
        : "r"(a[0]), "r"(a[1]), "r"(a[2]), "r"(a[3]), "r"(b0), "r"(b1));
}

// ---------------- kernel 1: convert inputs to bf16 + normalize labels ----------------
// 2048 blocks x 256 threads; each thread: 2 float4 loads -> 1 uint4 (16B) store
__global__ void prep_kernel(const float* __restrict__ x, const void* __restrict__ tgt){
    const int idx = blockIdx.x * blockDim.x + threadIdx.x;   // NPTS*DIM/8 threads
    const float4 v0 = ((const float4*)x)[2*idx];
    const float4 v1 = ((const float4*)x)[2*idx + 1];
    __nv_bfloat162 p0 = __float22bfloat162_rn(make_float2(v0.x, v0.y));
    __nv_bfloat162 p1 = __float22bfloat162_rn(make_float2(v0.z, v0.w));
    __nv_bfloat162 p2 = __float22bfloat162_rn(make_float2(v1.x, v1.y));
    __nv_bfloat162 p3 = __float22bfloat162_rn(make_float2(v1.z, v1.w));
    uint4 st;
    st.x = *(uint32_t*)&p0;
    st.y = *(uint32_t*)&p1;
    st.z = *(uint32_t*)&p2;
    st.w = *(uint32_t*)&p3;
    ((uint4*)g_X)[idx] = st;

    if (blockIdx.x == 0){
        // detect int64 vs int32 labels: values in [0,128); if int64, all odd words are 0
        const int* w = (const int*)tgt;
        bool is64 = true;
        #pragma unroll 1
        for (int k = 0; k < 64; k++)
            if (w[2*k + 1] != 0) { is64 = false; break; }
        if (is64){
            const long long* t64 = (const long long*)tgt;
            for (int i = threadIdx.x; i < NPTS; i += blockDim.x)
                g_lab[i] = (int)t64[i];
        } else {
            for (int i = threadIdx.x; i < NPTS; i += blockDim.x)
                g_lab[i] = w[i];
        }
    }
}

// ---------------- kernel 2: bf16 HMMA GEMM (exact R2 structure) + fused loss ----------------
__global__ void __launch_bounds__(256, 2) contrastive_gemm(){
    extern __shared__ char smem[];
    const uint32_t sb = smem_u32(smem);
    const int tid = threadIdx.x;
    const int wid = tid >> 5, lane = tid & 31;

    // map blockIdx.x -> upper-triangular (bi, bj), bi <= bj
    int bi = 0, rem = blockIdx.x;
    while (rem >= GB - bi){ rem -= GB - bi; bi++; }
    const int bj = bi + rem;
    const int i0 = bi * BM, j0 = bj * BN;
    const bool diag = (bi == bj);

    // labels into smem: ilab[128] @0, jlab[128] @512
    int* ilab = (int*)smem;
    int* jlab = (int*)(smem + 512);
    if (tid < 128) ilab[tid] = g_lab[i0 + tid];
    else           jlab[tid - 128] = g_lab[j0 + (tid - 128)];

    // cp.async loader: 256 threads, 8 threads x 16B per 128B row, 32 rows/pass
    const int rr = tid >> 3, vv = tid & 7;
    auto load_stage = [&](int c){
        const uint32_t sA = sb + 1024 + (c % STAGES) * STAGE_BYTES;
        const uint32_t sB = sA + 16384;
        const int kc = c * BK;
        #pragma unroll
        for (int p = 0; p < 4; p++){
            const int r = rr + p * 32;
            cp16(sA + SW128(r * 128 + vv * 16),
                 g_X + (size_t)(i0 + r) * DIM + kc + vv * 8);
            cp16(sB + SW128(r * 128 + vv * 16),
                 g_X + (size_t)(j0 + r) * DIM + kc + vv * 8);
        }
    };

    load_stage(0); CP_COMMIT();
    load_stage(1); CP_COMMIT();

    const int wm0 = (wid & 3) * 32;     // 4 warps in M
    const int wn0 = (wid >> 2) * 64;    // 2 warps in N

    float acc[2][8][4];                 // warp tile 32x64
    #pragma unroll
    for (int tm = 0; tm < 2; tm++)
        #pragma unroll
        for (int tn = 0; tn < 8; tn++)
            #pragma unroll
            for (int e = 0; e < 4; e++) acc[tm][tn][e] = 0.f;

    const int lrow = lane & 15, lhi = lane >> 4;

    for (int c = 0; c < NCHUNK; c++){
        CP_WAIT(1);
        __syncthreads();
        if (c + 2 < NCHUNK) load_stage(c + 2);
        CP_COMMIT();

        const uint32_t sA = sb + 1024 + (c % STAGES) * STAGE_BYTES;
        const uint32_t sB = sA + 16384;
        #pragma unroll
        for (int ks = 0; ks < 4; ks++){
            const int cb = ks * 32 + lhi * 16;
            uint32_t a[2][4];
            #pragma unroll
            for (int tm = 0; tm < 2; tm++)
                ldm_x4(a[tm], sA + SW128((wm0 + tm * 16 + lrow) * 128 + cb));
            uint32_t b[4][4];
            #pragma unroll
            for (int tp = 0; tp < 4; tp++)
                ldm_x4(b[tp], sB + SW128((wn0 + tp * 16 + lrow) * 128 + cb));
            #pragma unroll
            for (int tm = 0; tm < 2; tm++)
                #pragma unroll
                for (int tp = 0; tp < 4; tp++){
                    mma16816(acc[tm][2*tp],     a[tm], b[tp][0], b[tp][2]);
                    mma16816(acc[tm][2*tp + 1], a[tm], b[tp][1], b[tp][3]);
                }
        }
        __syncthreads();
    }

    // ---------------- fused masked loss on register accumulators ----------------
    const int r0 = lane >> 2, c0 = (lane & 3) * 2;
    float loss = 0.f;
    #pragma unroll
    for (int tm = 0; tm < 2; tm++){
        const int rowA = wm0 + tm * 16 + r0;
        const int liA  = ilab[rowA];
        const int liB  = ilab[rowA + 8];
        #pragma unroll
        for (int tn = 0; tn < 8; tn++){
            const int colb = wn0 + tn * 8 + c0;
            const int lj0 = jlab[colb], lj1 = jlab[colb + 1];
            #pragma unroll
            for (int e = 0; e < 4; e++){
                const float v = acc[tm][tn][e];
                const int row = (e >> 1) ? rowA + 8 : rowA;
                const int li  = (e >> 1) ? liB : liA;
                const int lj  = (e & 1) ? lj1 : lj0;
                float w = 2.f;
                if (diag){
                    const int gi = row, gj = colb + (e & 1);
                    w = (gi < gj) ? 2.f : ((gi == gj) ? 1.f : 0.f);
                }
                float l;
                if (li == lj) l = (v < 1.f) ? (1.f - v) : 0.f;
                else          l = (v > MARGINF) ? v : 0.f;
                loss += w * l;
            }
        }
    }

    // block reduction -> per-tile partial
    #pragma unroll
    for (int o = 16; o; o >>= 1) loss += __shfl_xor_sync(0xffffffffu, loss, o);
    __syncthreads();
    float* wsum = (float*)smem;
    if (lane == 0) wsum[wid] = loss;
    __syncthreads();
    if (tid == 0){
        float s = 0.f;
        #pragma unroll
        for (int w = 0; w < 8; w++) s += wsum[w];
        g_part[blockIdx.x] = s;
    }
}

// ---------------- kernel 3: deterministic final reduction ----------------
__global__ void reduce_kernel(float* __restrict__ out){
    __shared__ float sm[256];
    const int t = threadIdx.x;
    float v = 0.f;
    #pragma unroll 2
    for (int i = t; i < NPART; i += 256) v += g_part[i];
    sm[t] = v;
    __syncthreads();
    for (int s = 128; s > 0; s >>= 1){
        if (t < s) sm[t] += sm[t + s];
        __syncthreads();
    }
    if (t == 0) out[0] = sm[0] / (float)NPTS;
}

// ---------------- launch ----------------
extern "C" void kernel_launch(void* const* d_in, const int* in_sizes, int n_in,
                              void* d_out, int out_size){
    const float* x   = (const float*)d_in[0];
    const void*  tgt = d_in[1];
    float* out = (float*)d_out;

    cudaFuncSetAttribute(contrastive_gemm,
                         cudaFuncAttributeMaxDynamicSharedMemorySize, SMEM_BYTES);

    prep_kernel<<<NPTS*DIM/2048, 256>>>(x, tgt);
    contrastive_gemm<<<NPART, 256, SMEM_BYTES>>>();
    reduce_kernel<<<1, 256>>>(out);
}